// round 1
// baseline (speedup 1.0000x reference)
#include <cuda_runtime.h>
#include <cuda_bf16.h>

// Problem constants (from reference):
//   B=100, C2=128, H2=64  -> c2 [100,128,64,64], pixel (7,7) => offset 7*64+7 = 455
//   B=100, C3=256, H3=32  -> c3 [100,256,32,32], pixel (3,3) => offset 3*32+3 = 99
// Work: tm1 = (c2[b,c,7,7] > median1); sum (tm1-mask1)^2  (+ same for c3/median2/mask2)

#define B_   100
#define C2_  128
#define C3_  256
#define N1_  (B_ * C2_)          // 12800
#define N2_  (B_ * C3_)          // 25600
#define NT_  (N1_ + N2_)         // 38400
#define STRIDE1_ (64 * 64)       // 4096 elems per channel image
#define PIX1_    (7 * 64 + 7)    // 455
#define STRIDE2_ (32 * 32)       // 1024
#define PIX2_    (3 * 32 + 3)    // 99

__global__ void dsverifier_kernel(const float* __restrict__ c2,
                                  const float* __restrict__ c3,
                                  const float* __restrict__ mask1,
                                  const float* __restrict__ mask2,
                                  const float* __restrict__ median1,
                                  const float* __restrict__ median2,
                                  float* __restrict__ out)
{
    const float m1 = *median1;
    const float m2 = *median2;

    float acc = 0.0f;
    int idx = blockIdx.x * blockDim.x + threadIdx.x;
    const int gstride = gridDim.x * blockDim.x;

    for (int i = idx; i < NT_; i += gstride) {
        if (i < N1_) {
            // i = b*C2 + c ; c2 pixel at (b*C2 + c)*STRIDE1 + PIX1
            float v  = __ldg(&c2[(long long)i * STRIDE1_ + PIX1_]);
            float tm = (v > m1) ? 1.0f : 0.0f;
            float d  = tm - __ldg(&mask1[i]);
            acc += d * d;
        } else {
            int j = i - N1_;
            float v  = __ldg(&c3[(long long)j * STRIDE2_ + PIX2_]);
            float tm = (v > m2) ? 1.0f : 0.0f;
            float d  = tm - __ldg(&mask2[j]);
            acc += d * d;
        }
    }

    // warp reduce
    #pragma unroll
    for (int off = 16; off > 0; off >>= 1)
        acc += __shfl_down_sync(0xFFFFFFFFu, acc, off);

    // block reduce via smem
    __shared__ float warp_sums[32];
    int lane = threadIdx.x & 31;
    int wid  = threadIdx.x >> 5;
    if (lane == 0) warp_sums[wid] = acc;
    __syncthreads();

    if (wid == 0) {
        int nwarps = (blockDim.x + 31) >> 5;
        float v = (lane < nwarps) ? warp_sums[lane] : 0.0f;
        #pragma unroll
        for (int off = 16; off > 0; off >>= 1)
            v += __shfl_down_sync(0xFFFFFFFFu, v, off);
        if (lane == 0)
            atomicAdd(out, v);
    }
}

extern "C" void kernel_launch(void* const* d_in, const int* in_sizes, int n_in,
                              void* d_out, int out_size)
{
    const float* c2      = (const float*)d_in[0];
    const float* c3      = (const float*)d_in[1];
    const float* mask1   = (const float*)d_in[2];
    const float* mask2   = (const float*)d_in[3];
    const float* median1 = (const float*)d_in[4];
    const float* median2 = (const float*)d_in[5];
    float* out = (float*)d_out;

    // d_out is poisoned; zero it (graph-capturable async memset)
    cudaMemsetAsync(out, 0, sizeof(float));

    const int threads = 256;
    const int blocks  = (NT_ + threads - 1) / threads;   // 150 blocks -> ~1 wave
    dsverifier_kernel<<<blocks, threads>>>(c2, c3, mask1, mask2, median1, median2, out);
}